// round 1
// baseline (speedup 1.0000x reference)
#include <cuda_runtime.h>
#include <math.h>

// Problem constants
#define L_SEQ 2048
#define B_SZ  32
#define DIN   128
#define DST   512

// Recurrent kernel partitioning: 128 persistent CTAs = 16 h-groups x 8 batch-groups
#define NCTA  128
#define HG_N  16
#define BG_N  8
#define RH    32   // h rows per CTA  (DST / HG_N)
#define NB    4    // batches per CTA (B_SZ / BG_N)

// Scratch (device globals per allocation rules)
__device__ float g_pre[L_SEQ * B_SZ * DST];   // [l][b][h] pre-activations
__device__ float g_hs [L_SEQ * B_SZ * DST];   // [l][b][h] hidden states
__device__ unsigned g_count;                  // global barrier arrival counter

union F4U  { float4 f4; ulonglong2 u2; };
union U64F { unsigned long long u; float2 f; };

__device__ __forceinline__ void ffma2(unsigned long long& acc,
                                      unsigned long long a,
                                      unsigned long long b) {
    asm volatile("fma.rn.f32x2 %0, %1, %2, %0;" : "+l"(acc) : "l"(a), "l"(b));
}

// ---------------------------------------------------------------------------
// Kernel 1: pre[l][b][h] = b_ih[h] + b_hh[h] + sum_d x[b][d][l] * W_ih[h][d]
// One block per l. x slice staged in smem; W_ih rows broadcast from L2.
// Output staged through smem for coalesced global writes.
// ---------------------------------------------------------------------------
__global__ void __launch_bounds__(256) k_pre(const float* __restrict__ x,
                                             const float* __restrict__ Wih,
                                             const float* __restrict__ bih,
                                             const float* __restrict__ bhh) {
    extern __shared__ float smem_dyn[];
    float* x_s   = smem_dyn;               // [32][132] padded
    float* out_s = smem_dyn + B_SZ * 132;  // [512][33] padded

    const int l = blockIdx.x;
    const int t = threadIdx.x;

    // Stage x[:, :, l] (strided gather from global)
    for (int idx = t; idx < B_SZ * DIN; idx += 256) {
        int b = idx >> 7, d = idx & 127;
        x_s[b * 132 + d] = x[(b * DIN + d) * L_SEQ + l];
    }
    __syncthreads();

    const int b  = t & 31;
    const int hb = t >> 5;  // 0..7, each covers 64 h values

    for (int j = 0; j < 64; j++) {
        const int h = hb * 64 + j;
        const float* wr = Wih + h * DIN;
        unsigned long long a0 = 0ull, a1 = 0ull;
#pragma unroll
        for (int d = 0; d < DIN; d += 4) {
            F4U xv; xv.f4 = *(const float4*)(x_s + b * 132 + d);
            F4U wv; wv.f4 = *(const float4*)(wr + d);
            ffma2(a0, xv.u2.x, wv.u2.x);
            ffma2(a1, xv.u2.y, wv.u2.y);
        }
        U64F u0, u1; u0.u = a0; u1.u = a1;
        out_s[h * 33 + b] = u0.f.x + u0.f.y + u1.f.x + u1.f.y + bih[h] + bhh[h];
    }
    __syncthreads();

    float* pr = g_pre + (size_t)l * B_SZ * DST;
    for (int idx = t; idx < B_SZ * DST; idx += 256) {
        int bb = idx >> 9, h = idx & 511;
        pr[idx] = out_s[h * 33 + bb];
    }
}

// ---------------------------------------------------------------------------
// Kernel 2: persistent recurrent scan. 128 CTAs, each owns 32 h rows x 4 batches.
// W_hh slice lives in REGISTERS (64 floats/thread, constant across all steps).
// Per step: read h_{l-1} slice from L2, FFMA2 dot products, tanh, write h_l,
// global sense-free monotonic-counter barrier.
// ---------------------------------------------------------------------------
__global__ void __launch_bounds__(256, 1) k_rnn(const float* __restrict__ Whh) {
    __shared__ float h_s[NB * DST];          // 8 KB: our 4 batches' h_{l-1}
    __shared__ float red[NB * 8 * RH];       // 4 KB: partial sums

    const int t   = threadIdx.x;
    const int cta = blockIdx.x;
    const int hg  = cta & (HG_N - 1);
    const int bg  = cta >> 4;
    const int r   = t & 31;   // row within h-group
    const int ks  = t >> 5;   // K slice 0..7 (each 64 wide)

    // Cache this thread's W_hh row slice in registers (never changes)
    F4U wreg[16];
    {
        const float* wr = Whh + (hg * RH + r) * DST + ks * 64;
#pragma unroll
        for (int i = 0; i < 16; i++) wreg[i].f4 = *(const float4*)(wr + 4 * i);
    }

    for (int l = 0; l < L_SEQ; l++) {
        // Load h_{l-1} for our 4 batches (or zeros at l==0)
        if (l == 0) {
            for (int idx = t; idx < NB * DST; idx += 256) h_s[idx] = 0.f;
        } else {
            const float* hp = g_hs + ((size_t)(l - 1) * B_SZ + bg * NB) * DST;
            for (int idx = t * 4; idx < NB * DST; idx += 1024)
                *(float4*)(h_s + idx) = *(const float4*)(hp + idx);
        }
        float pv = 0.f;
        if (t < NB * RH) {
            int b = t >> 5, rr = t & 31;
            pv = g_pre[((size_t)l * B_SZ + bg * NB + b) * DST + hg * RH + rr];
        }
        __syncthreads();

        // Partial dot products: thread (r, ks) x all 4 batches
#pragma unroll
        for (int b = 0; b < NB; b++) {
            const float* hr = h_s + b * DST + ks * 64;
            unsigned long long a0 = 0ull, a1 = 0ull;
#pragma unroll
            for (int i = 0; i < 16; i++) {
                F4U hv; hv.f4 = *(const float4*)(hr + 4 * i);
                ffma2(a0, hv.u2.x, wreg[i].u2.x);
                ffma2(a1, hv.u2.y, wreg[i].u2.y);
            }
            U64F u0, u1; u0.u = a0; u1.u = a1;
            red[(b * 8 + ks) * RH + r] = u0.f.x + u0.f.y + u1.f.x + u1.f.y;
        }
        __syncthreads();

        // Reduce 8 K-slices, add pre, tanh, write h_l
        if (t < NB * RH) {
            int b = t >> 5, rr = t & 31;
            float s = pv;
#pragma unroll
            for (int k2 = 0; k2 < 8; k2++) s += red[(b * 8 + k2) * RH + rr];
            float hv = tanhf(s);
            g_hs[((size_t)l * B_SZ + bg * NB + b) * DST + hg * RH + rr] = hv;
        }

        // Global barrier (skip after the final step)
        if (l < L_SEQ - 1) {
            __threadfence();
            __syncthreads();
            if (t == 0) {
                unsigned target = (unsigned)(l + 1) * NCTA;
                unsigned* cp = &g_count;
                asm volatile("red.release.gpu.add.u32 [%0], %1;"
                             :: "l"(cp), "r"(1u) : "memory");
                unsigned v;
                do {
                    asm volatile("ld.acquire.gpu.u32 %0, [%1];"
                                 : "=r"(v) : "l"(cp) : "memory");
                } while (v < target);
            }
            __syncthreads();
        }
    }
}

// ---------------------------------------------------------------------------
// Kernel 3: y[lb][o] = tanh(b_fc[o] + sum_k hs[lb][k] * W_fc[o][k])
// One block per 32 lb rows. hs tile in smem, W_fc rows broadcast from L2.
// ---------------------------------------------------------------------------
__global__ void __launch_bounds__(256) k_out(const float* __restrict__ Wfc,
                                             const float* __restrict__ bfc,
                                             float* __restrict__ y) {
    extern __shared__ float smem_dyn[];
    float* h_s   = smem_dyn;                // [32][516] padded
    float* out_s = smem_dyn + 32 * 516;     // [128][33] padded

    const int t = threadIdx.x;
    const size_t base = (size_t)blockIdx.x * 32;  // first lb row

    const float* hp = g_hs + base * DST;
    for (int idx = t; idx < 4096; idx += 256) {
        int row = idx >> 7, kk = (idx & 127) * 4;
        *(float4*)(h_s + row * 516 + kk) = *(const float4*)(hp + row * DST + kk);
    }
    __syncthreads();

    const int row = t & 31;
    const int ob  = t >> 5;  // 0..7, each covers 16 outputs

    for (int j = 0; j < 16; j++) {
        const int o = ob * 16 + j;
        const float* wr = Wfc + o * DST;
        unsigned long long a0 = 0ull, a1 = 0ull;
#pragma unroll 8
        for (int k = 0; k < DST; k += 4) {
            F4U hv; hv.f4 = *(const float4*)(h_s + row * 516 + k);
            F4U wv; wv.f4 = *(const float4*)(wr + k);
            ffma2(a0, hv.u2.x, wv.u2.x);
            ffma2(a1, hv.u2.y, wv.u2.y);
        }
        U64F u0, u1; u0.u = a0; u1.u = a1;
        out_s[o * 33 + row] = tanhf(u0.f.x + u0.f.y + u1.f.x + u1.f.y + bfc[o]);
    }
    __syncthreads();

    float* yp = y + base * DIN;
    for (int idx = t; idx < 32 * DIN; idx += 256) {
        int rr = idx >> 7, o = idx & 127;
        yp[idx] = out_s[o * 33 + rr];
    }
}

// ---------------------------------------------------------------------------
extern "C" void kernel_launch(void* const* d_in, const int* in_sizes, int n_in,
                              void* d_out, int out_size) {
    const float* x   = (const float*)d_in[0];
    const float* Wih = (const float*)d_in[1];
    const float* Whh = (const float*)d_in[2];
    const float* bih = (const float*)d_in[3];
    const float* bhh = (const float*)d_in[4];
    const float* Wfc = (const float*)d_in[5];
    const float* bfc = (const float*)d_in[6];
    float* y = (float*)d_out;

    cudaFuncSetAttribute(k_pre, cudaFuncAttributeMaxDynamicSharedMemorySize,
                         (B_SZ * 132 + DST * 33) * (int)sizeof(float));
    cudaFuncSetAttribute(k_out, cudaFuncAttributeMaxDynamicSharedMemorySize,
                         (32 * 516 + 128 * 33) * (int)sizeof(float));

    void* cnt = nullptr;
    cudaGetSymbolAddress(&cnt, g_count);
    cudaMemsetAsync(cnt, 0, sizeof(unsigned), 0);

    k_pre<<<L_SEQ, 256, (B_SZ * 132 + DST * 33) * sizeof(float)>>>(x, Wih, bih, bhh);
    k_rnn<<<NCTA, 256>>>(Whh);
    k_out<<<(L_SEQ * B_SZ) / 32, 256, (32 * 516 + 128 * 33) * sizeof(float)>>>(Wfc, bfc, y);
}

// round 3
// speedup vs baseline: 1.3584x; 1.3584x over previous
#include <cuda_runtime.h>
#include <math.h>
#include <stdint.h>

// Problem constants
#define L_SEQ 2048
#define B_SZ  32
#define DIN   128
#define DST   512

// Scratch (device globals per allocation rules)
__device__ float g_pre[L_SEQ * B_SZ * DST];   // [l][b][h]
__device__ float g_hs [L_SEQ * B_SZ * DST];   // [l][b][h]

union F4U  { float4 f4; ulonglong2 u2; };
union U64F { unsigned long long u; float2 f; };

__device__ __forceinline__ void ffma2(unsigned long long& acc,
                                      unsigned long long a,
                                      unsigned long long b) {
    asm volatile("fma.rn.f32x2 %0, %1, %2, %0;" : "+l"(acc) : "l"(a), "l"(b));
}

__device__ __forceinline__ uint32_t smem_u32(const void* p) {
    return (uint32_t)__cvta_generic_to_shared(p);
}

__device__ __forceinline__ void mbar_wait_cluster(uint32_t addr, uint32_t parity) {
    asm volatile(
        "{\n\t"
        ".reg .pred P;\n\t"
        "WAIT%=:\n\t"
        "mbarrier.try_wait.parity.acquire.cluster.shared::cta.b64 P, [%0], %1;\n\t"
        "@!P bra WAIT%=;\n\t"
        "}\n"
        :: "r"(addr), "r"(parity) : "memory");
}

// ---------------------------------------------------------------------------
// Kernel 1: pre[l][b][h] = b_ih[h]+b_hh[h] + sum_d x[b][d][l] * W_ih[h][d]
// Grid (2048 l, 4 hblk). Register-tiled GEMM: thread tile 4b x 4h, f32x2 over
// h-pairs, k-major smem staging.
// ---------------------------------------------------------------------------
#define PRE_SMEM ((128 * 36 + 128 * 132) * 4)

__global__ void __launch_bounds__(256) k_pre(const float* __restrict__ x,
                                             const float* __restrict__ Wih,
                                             const float* __restrict__ bih,
                                             const float* __restrict__ bhh) {
    extern __shared__ float sm[];
    float* x_s = sm;              // [128 d][36]  (b-major, padded)
    float* w_s = sm + 128 * 36;   // [128 d][132] (h-major, padded)

    const int l  = blockIdx.x;
    const int hb = blockIdx.y;    // 0..3 -> 128 h each
    const int t  = threadIdx.x;

    for (int idx = t; idx < 32 * 128; idx += 256) {
        int b = idx & 31, d = idx >> 5;
        x_s[d * 36 + b] = x[((size_t)b * DIN + d) * L_SEQ + l];
    }
    for (int idx = t; idx < 128 * 128; idx += 256) {
        int d = idx & 127, h = idx >> 7;
        w_s[d * 132 + h] = Wih[(size_t)(hb * 128 + h) * DIN + d];
    }
    __syncthreads();

    const int tx = t & 31;   // h-tile: h = hb*128 + 4*tx ..
    const int ty = t >> 5;   // b-tile: b = 4*ty ..

    unsigned long long acc[4][2];
#pragma unroll
    for (int i = 0; i < 4; i++) { acc[i][0] = 0ull; acc[i][1] = 0ull; }

#pragma unroll 4
    for (int k = 0; k < 128; k++) {
        F4U wv; wv.f4 = *(const float4*)(w_s + k * 132 + tx * 4);
        F4U xv; xv.f4 = *(const float4*)(x_s + k * 36 + ty * 4);
        float xs[4] = {xv.f4.x, xv.f4.y, xv.f4.z, xv.f4.w};
#pragma unroll
        for (int b = 0; b < 4; b++) {
            U64F d2; d2.f.x = xs[b]; d2.f.y = xs[b];
            ffma2(acc[b][0], wv.u2.x, d2.u);
            ffma2(acc[b][1], wv.u2.y, d2.u);
        }
    }

    const int h0 = hb * 128 + tx * 4;
    float4 bi = *(const float4*)(bih + h0);
    float4 bh = *(const float4*)(bhh + h0);
    float4 bias = {bi.x + bh.x, bi.y + bh.y, bi.z + bh.z, bi.w + bh.w};
#pragma unroll
    for (int b = 0; b < 4; b++) {
        U64F u0, u1; u0.u = acc[b][0]; u1.u = acc[b][1];
        float4 o = {u0.f.x + bias.x, u0.f.y + bias.y,
                    u1.f.x + bias.z, u1.f.y + bias.w};
        *(float4*)(g_pre + ((size_t)l * B_SZ + ty * 4 + b) * DST + h0) = o;
    }
}

// ---------------------------------------------------------------------------
// Kernel 2: recurrent scan. 16 clusters x 8 CTAs. Cluster owns 2 batches; CTA
// rank owns h rows [64*rank, 64*rank+64). W_hh slice in registers.
// h exchange via DSMEM push-stores; sync via double-buffered remote mbarriers.
// Last step does NO remote traffic; trailing cluster barrier before exit.
// ---------------------------------------------------------------------------
__global__ void __launch_bounds__(256, 1) __cluster_dims__(8, 1, 1)
k_rnn(const float* __restrict__ Whh) {
    __shared__ float hbuf[2][2 * DST];   // double-buffered full h for 2 batches
    __shared__ float red[4][2][64];      // partials: [kslice][batch][row]
    __shared__ __align__(8) unsigned long long barr[2];

    const int t = threadIdx.x;
    uint32_t rank;
    asm("mov.u32 %0, %%cluster_ctarank;" : "=r"(rank));
    const int cl = blockIdx.x >> 3;      // cluster id 0..15
    const int r  = t & 63;               // row within my 64-row slice
    const int ks = t >> 6;               // K slice 0..3 (128 wide)

    // W_hh slice -> registers (constant across all steps)
    F4U w[32];
    {
        const float4* wp = (const float4*)(Whh + (size_t)(rank * 64 + r) * DST + ks * 128);
#pragma unroll
        for (int i = 0; i < 32; i++) w[i].f4 = wp[i];
    }

    // h_{-1} = 0 lives in buffer 1 (step 0 reads buf[(0-1)&1] = buf[1])
    for (int i = t; i < 2 * DST; i += 256) hbuf[1][i] = 0.f;

    uint32_t bar0 = smem_u32(&barr[0]);
    if (t == 0) {
        asm volatile("mbarrier.init.shared.b64 [%0], %1;" :: "r"(bar0), "r"(8u) : "memory");
        asm volatile("mbarrier.init.shared.b64 [%0], %1;" :: "r"(bar0 + 8), "r"(8u) : "memory");
        asm volatile("fence.mbarrier_init.release.cluster;" ::: "memory");
    }
    __syncthreads();
    // all peers' barriers initialized before any remote arrive
    asm volatile("barrier.cluster.arrive.aligned;" ::: "memory");
    asm volatile("barrier.cluster.wait.aligned;" ::: "memory");

    const uint32_t hbase = smem_u32(&hbuf[0][0]);
    uint32_t peer_h[8], peer_b[8];
#pragma unroll
    for (int p = 0; p < 8; p++) {
        asm("mapa.shared::cluster.u32 %0, %1, %2;" : "=r"(peer_h[p]) : "r"(hbase), "r"(p));
        asm("mapa.shared::cluster.u32 %0, %1, %2;" : "=r"(peer_b[p]) : "r"(bar0), "r"(p));
    }

    const int b0 = cl * 2;
    const int tb = t >> 6;   // (t<128): batch 0/1
    const int tr = t & 63;   // (t<128): row
    const size_t outoff = (size_t)(b0 + tb) * DST + rank * 64 + tr;

    for (int l = 0; l < L_SEQ; l++) {
        const int cur = l & 1, prev = cur ^ 1;

        // prefetch pre-activation (independent of the barrier)
        float pv = 0.f;
        if (t < 128) pv = __ldg(g_pre + (size_t)l * (B_SZ * DST) + outoff);

        if (l > 0) mbar_wait_cluster(bar0 + 8u * (uint32_t)prev, ((l - 1) >> 1) & 1);

        // partial matvec: rows owned by this CTA, K slice owned by this thread
        const float* hbp = hbuf[prev];
#pragma unroll
        for (int b = 0; b < 2; b++) {
            const float4* hp = (const float4*)(hbp + b * DST + ks * 128);
            unsigned long long a0 = 0ull, a1 = 0ull;
#pragma unroll
            for (int i = 0; i < 32; i++) {
                F4U hv; hv.f4 = hp[i];
                ffma2(a0, hv.u2.x, w[i].u2.x);
                ffma2(a1, hv.u2.y, w[i].u2.y);
            }
            U64F u0, u1; u0.u = a0; u1.u = a1;
            red[ks][b][r] = u0.f.x + u0.f.y + u1.f.x + u1.f.y;
        }
        __syncthreads();

        if (t < 128) {
            float s = pv + red[0][tb][tr] + red[1][tb][tr]
                         + red[2][tb][tr] + red[3][tb][tr];
            float hv = tanhf(s);
            g_hs[(size_t)l * (B_SZ * DST) + outoff] = hv;
            // push my h into every cluster CTA's next buffer (not on last step:
            // after each peer's final wait, nothing may target its smem)
            if (l < L_SEQ - 1) {
                uint32_t off = (uint32_t)((cur * 2 * DST + tb * DST + (int)rank * 64 + tr) * 4);
#pragma unroll
                for (int p = 0; p < 8; p++)
                    asm volatile("st.shared::cluster.f32 [%0], %1;"
                                 :: "r"(peer_h[p] + off), "f"(hv) : "memory");
            }
        }
        __syncthreads();

        if (l < L_SEQ - 1 && t < 8)
            asm volatile("mbarrier.arrive.release.cluster.shared::cluster.b64 _, [%0];"
                         :: "r"(peer_b[t] + 8u * (uint32_t)cur) : "memory");
    }

    // No CTA may exit while peers could still touch its smem.
    asm volatile("barrier.cluster.arrive.aligned;" ::: "memory");
    asm volatile("barrier.cluster.wait.aligned;" ::: "memory");
}

// ---------------------------------------------------------------------------
// Kernel 3: y[lb][o] = tanh(b_fc[o] + sum_k hs[lb][k] * W_fc[o][k])
// Block: 64 lb x 128 o, thread tile 8 lb x 4 o, K chunked by 128.
// ---------------------------------------------------------------------------
#define OUT_SMEM ((128 * 68 + 128 * 132) * 4)

__global__ void __launch_bounds__(256) k_out(const float* __restrict__ Wfc,
                                             const float* __restrict__ bfc,
                                             float* __restrict__ y) {
    extern __shared__ float sm[];
    float* a_s = sm;              // [128 k][68]  (lb-major, padded)
    float* w_s = sm + 128 * 68;   // [128 k][132] (o-major, padded)

    const int t = threadIdx.x;
    const size_t base = (size_t)blockIdx.x * 64;
    const int tx = t & 31;   // o-tile: o = 4*tx ..
    const int ty = t >> 5;   // lb-tile: lb = base + 8*ty ..

    unsigned long long acc[8][2];
#pragma unroll
    for (int i = 0; i < 8; i++) { acc[i][0] = 0ull; acc[i][1] = 0ull; }

    for (int kc = 0; kc < 4; kc++) {
        __syncthreads();
        for (int idx = t; idx < 64 * 128; idx += 256) {
            int kk = idx & 127, row = idx >> 7;
            a_s[kk * 68 + row] = g_hs[(base + row) * DST + kc * 128 + kk];
        }
        for (int idx = t; idx < 128 * 128; idx += 256) {
            int kk = idx & 127, o = idx >> 7;
            w_s[kk * 132 + o] = Wfc[(size_t)o * DST + kc * 128 + kk];
        }
        __syncthreads();

#pragma unroll 2
        for (int k = 0; k < 128; k++) {
            F4U wv; wv.f4 = *(const float4*)(w_s + k * 132 + tx * 4);
            F4U a0; a0.f4 = *(const float4*)(a_s + k * 68 + ty * 8);
            F4U a1; a1.f4 = *(const float4*)(a_s + k * 68 + ty * 8 + 4);
            float av[8] = {a0.f4.x, a0.f4.y, a0.f4.z, a0.f4.w,
                           a1.f4.x, a1.f4.y, a1.f4.z, a1.f4.w};
#pragma unroll
            for (int rr = 0; rr < 8; rr++) {
                U64F d2; d2.f.x = av[rr]; d2.f.y = av[rr];
                ffma2(acc[rr][0], wv.u2.x, d2.u);
                ffma2(acc[rr][1], wv.u2.y, d2.u);
            }
        }
    }

    const int o0 = tx * 4;
    float4 bi = *(const float4*)(bfc + o0);
#pragma unroll
    for (int rr = 0; rr < 8; rr++) {
        U64F u0, u1; u0.u = acc[rr][0]; u1.u = acc[rr][1];
        float4 o = {tanhf(u0.f.x + bi.x), tanhf(u0.f.y + bi.y),
                    tanhf(u1.f.x + bi.z), tanhf(u1.f.y + bi.w)};
        *(float4*)(y + (base + ty * 8 + rr) * DIN + o0) = o;
    }
}

// ---------------------------------------------------------------------------
extern "C" void kernel_launch(void* const* d_in, const int* in_sizes, int n_in,
                              void* d_out, int out_size) {
    const float* x   = (const float*)d_in[0];
    const float* Wih = (const float*)d_in[1];
    const float* Whh = (const float*)d_in[2];
    const float* bih = (const float*)d_in[3];
    const float* bhh = (const float*)d_in[4];
    const float* Wfc = (const float*)d_in[5];
    const float* bfc = (const float*)d_in[6];
    float* y = (float*)d_out;

    cudaFuncSetAttribute(k_pre, cudaFuncAttributeMaxDynamicSharedMemorySize, PRE_SMEM);
    cudaFuncSetAttribute(k_out, cudaFuncAttributeMaxDynamicSharedMemorySize, OUT_SMEM);

    k_pre<<<dim3(L_SEQ, 4), 256, PRE_SMEM>>>(x, Wih, bih, bhh);
    k_rnn<<<128, 256>>>(Whh);
    k_out<<<(L_SEQ * B_SZ) / 64, 256, OUT_SMEM>>>(Wfc, bfc, y);
}